// round 6
// baseline (speedup 1.0000x reference)
#include <cuda_runtime.h>
#include <math.h>
#include <float.h>
#include <stdint.h>

#define BB   8
#define NN   512
#define CC   256
#define HE   32
#define F0   64
#define OUTD 2
#define MTOT (BB*NN)   // 4096

// ---------------- scratch (device globals; no allocations) ----------------
__device__ float g_xab[MTOT*64];     // [xa | xb+eb1] per row
__device__ float g_Ap[BB*NN*NN];     // raw A_pred (8 MB)
__device__ float g_S0[MTOT];
__device__ float g_S1[MTOT];
__device__ float g_P0[MTOT*F0];      // D-scaled projections (tf32-rounded)
__device__ float g_P1[MTOT*F0];
__device__ float g_Y0[MTOT*F0];
__device__ float g_Y1[MTOT*F0];

// ---------------- helpers ----------------
__device__ __forceinline__ float tf32_rn(float x) {
    uint32_t u;
    asm("cvt.rna.tf32.f32 %0, %1;" : "=r"(u) : "f"(x));
    return __uint_as_float(u);
}
__device__ __forceinline__ void mma_tf32(float c[4], const uint32_t a[4], const uint32_t b[2]) {
    asm volatile(
        "mma.sync.aligned.m16n8k8.row.col.f32.tf32.tf32.f32 "
        "{%0,%1,%2,%3}, {%4,%5,%6,%7}, {%8,%9}, {%0,%1,%2,%3};\n"
        : "+f"(c[0]), "+f"(c[1]), "+f"(c[2]), "+f"(c[3])
        : "r"(a[0]), "r"(a[1]), "r"(a[2]), "r"(a[3]), "r"(b[0]), "r"(b[1]));
}
__device__ __forceinline__ float dinv(float s) { return rsqrtf(s + 1.0f + 1e-5f); }

// ---------------- zero colsum accumulators ----------------
__global__ __launch_bounds__(256) void k_zeroS() {
    int i = blockIdx.x*256 + threadIdx.x;
    if (i < MTOT) { g_S0[i] = 0.f; g_S1[i] = 0.f; }
}

// ---------------- g_xab = x @ [wa | wb], eb1 folded into cols 32..63 ----------------
__global__ __launch_bounds__(256) void k_xab(const float* __restrict__ x,
                                             const float* __restrict__ ew1,
                                             const float* __restrict__ eb1) {
    int m0 = blockIdx.x*64;
    __shared__ float As[16][64];
    __shared__ float Bs[16][64];
    int t = threadIdx.x;
    int tx = t & 15, ty = t >> 4;
    float acc[4][4] = {};

    for (int k0 = 0; k0 < CC; k0 += 16) {
        {
            int row = t >> 2, kq = (t & 3)*4;
            float4 v = *(const float4*)&x[(size_t)(m0+row)*CC + k0 + kq];
            As[kq+0][row] = v.x; As[kq+1][row] = v.y; As[kq+2][row] = v.z; As[kq+3][row] = v.w;
        }
        {
            int kk = t >> 4, nq = (t & 15)*4;
            const float* src = (nq < 32) ? &ew1[(size_t)(k0+kk)*HE + nq]
                                         : &ew1[(size_t)(k0+kk+CC)*HE + nq - 32];
            *(float4*)&Bs[kk][nq] = *(const float4*)src;
        }
        __syncthreads();
#pragma unroll
        for (int k = 0; k < 16; ++k) {
            float4 a = *(const float4*)&As[k][ty*4];
            float4 bv = *(const float4*)&Bs[k][tx*4];
            float av[4] = {a.x, a.y, a.z, a.w};
            float bb[4] = {bv.x, bv.y, bv.z, bv.w};
#pragma unroll
            for (int u = 0; u < 4; ++u)
#pragma unroll
                for (int v2 = 0; v2 < 4; ++v2)
                    acc[u][v2] = fmaf(av[u], bb[v2], acc[u][v2]);
        }
        __syncthreads();
    }
#pragma unroll
    for (int u = 0; u < 4; ++u) {
        int row = m0 + ty*4 + u;
        float o[4];
#pragma unroll
        for (int v2 = 0; v2 < 4; ++v2) {
            int col = tx*4 + v2;
            o[v2] = acc[u][v2] + (col >= 32 ? eb1[col-32] : 0.f);
        }
        *(float4*)&g_xab[(size_t)row*64 + tx*4] = make_float4(o[0], o[1], o[2], o[3]);
    }
}

// ---------------- colsum of input A (512 blocks) ----------------
__global__ __launch_bounds__(256) void k_colsumA(const float* __restrict__ A) {
    int b = blockIdx.y, r0 = blockIdx.x*8;
    int t = threadIdx.x;
    float a0 = 0.f, a1 = 0.f;
    const float* base = A + ((size_t)b*NN + r0)*NN;
#pragma unroll
    for (int r = 0; r < 8; ++r) {
        a0 += base[r*NN + t];
        a1 += base[r*NN + t + 256];
    }
    atomicAdd(&g_S0[b*NN + t],       a0);
    atomicAdd(&g_S0[b*NN + t + 256], a1);
}

// ---------------- fused edge-MLP + symmetrize + exp + mask + colsum(S1) ----------------
__global__ __launch_bounds__(256) void k_edge_sym(const float* __restrict__ mask,
                                                  const float* __restrict__ ew2,
                                                  const float* __restrict__ eb2) {
    int idx = blockIdx.x, bi = 0;
    while (idx >= 16 - bi) { idx -= 16 - bi; ++bi; }
    int bj = bi + idx;
    int b = blockIdx.y;
    int i0 = bi*32, j0 = bj*32;
    bool diag = (bi == bj);
    __shared__ float si[32][68], sj[32][68];
    __shared__ float w[32], mi_s[32], mj_s[32];
    __shared__ float red[8][32];
    int tx = threadIdx.x, ty = threadIdx.y;
    int t = ty*32 + tx;
    for (int q = t; q < 512; q += 256) {
        int r = q >> 4, c = (q & 15)*4;
        *(float4*)&si[r][c] = *(const float4*)&g_xab[(size_t)(b*NN + i0 + r)*64 + c];
        *(float4*)&sj[r][c] = *(const float4*)&g_xab[(size_t)(b*NN + j0 + r)*64 + c];
    }
    if (t < 32) { w[t] = ew2[t]; mi_s[t] = mask[b*NN + i0 + t]; mj_s[t] = mask[b*NN + j0 + t]; }
    __syncthreads();

    float raj[32], rbj[32];
#pragma unroll
    for (int c = 0; c < 32; c += 4) {
        float4 a = *(const float4*)&sj[tx][c];
        raj[c] = a.x; raj[c+1] = a.y; raj[c+2] = a.z; raj[c+3] = a.w;
        float4 bq = *(const float4*)&sj[tx][32 + c];
        rbj[c] = bq.x; rbj[c+1] = bq.y; rbj[c+2] = bq.z; rbj[c+3] = bq.w;
    }

    float e2v = eb2[0];
    float colacc = 0.f;
#pragma unroll
    for (int r = 0; r < 4; ++r) {
        int il = ty + r*8, jl = tx;
        float acc1 = e2v, acc2 = e2v;
#pragma unroll
        for (int k = 0; k < 32; ++k) {
            float ai = si[il][k];
            float bi_ = si[il][32 + k];
            acc1 = fmaf(fmaxf(ai + rbj[k], 0.f), w[k], acc1);
            acc2 = fmaf(fmaxf(raj[k] + bi_, 0.f), w[k], acc2);
        }
        int gi = i0 + il, gj = j0 + jl;
        float v = 0.f;
        if (gi != gj && mi_s[il] > 0.f && mj_s[jl] > 0.f)
            v = __expf(0.5f*(acc1 + acc2));
        g_Ap[((size_t)b*NN + gi)*NN + gj] = v;
        colacc += v;
        if (!diag) {
            g_Ap[((size_t)b*NN + gj)*NN + gi] = v;
            float rs = v;
#pragma unroll
            for (int off = 16; off; off >>= 1) rs += __shfl_xor_sync(0xffffffffu, rs, off);
            if (tx == 0) atomicAdd(&g_S1[b*NN + gi], rs);
        }
    }
    red[ty][tx] = colacc;
    __syncthreads();
    if (ty == 0) {
        float tot = 0.f;
#pragma unroll
        for (int q = 0; q < 8; ++q) tot += red[q][tx];
        atomicAdd(&g_S1[b*NN + j0 + tx], tot);
    }
}

// ---------------- projection: P_s = tf32(D_s * (h @ W_s)), D inline ----------------
__global__ __launch_bounds__(256) void k_proj(const float* __restrict__ xin,
                                              const float* __restrict__ biasPrev,
                                              const float* __restrict__ W,
                                              const float* __restrict__ mask,
                                              int mode, int K) {
    int m0 = blockIdx.x*64;
    int s = blockIdx.y;
    const float* Wp = W + (size_t)s*K*F0;
    const float* Sp = s ? g_S1 : g_S0;
    float* P = s ? g_P1 : g_P0;

    __shared__ float As[16][64];
    __shared__ float Bs[16][64];
    int t = threadIdx.x;
    int tx = t & 15, ty = t >> 4;
    float acc[4][4] = {};

    for (int k0 = 0; k0 < K; k0 += 16) {
        {
            int row = t >> 2, kq = (t & 3)*4;
            int grow = m0 + row;
            float4 v;
            if (mode == 0) {
                v = *(const float4*)&xin[(size_t)grow*CC + k0 + kq];
            } else {
                float4 y0 = *(const float4*)&g_Y0[(size_t)grow*F0 + k0 + kq];
                float4 y1 = *(const float4*)&g_Y1[(size_t)grow*F0 + k0 + kq];
                float4 bp = *(const float4*)&biasPrev[k0 + kq];
                float mk = mask[grow];
                v.x = fmaxf((y0.x + y1.x + bp.x)*mk, 0.f);
                v.y = fmaxf((y0.y + y1.y + bp.y)*mk, 0.f);
                v.z = fmaxf((y0.z + y1.z + bp.z)*mk, 0.f);
                v.w = fmaxf((y0.w + y1.w + bp.w)*mk, 0.f);
            }
            As[kq+0][row] = v.x; As[kq+1][row] = v.y; As[kq+2][row] = v.z; As[kq+3][row] = v.w;
        }
        {
            int kk = t >> 4, nq = (t & 15)*4;
            *(float4*)&Bs[kk][nq] = *(const float4*)&Wp[(size_t)(k0+kk)*F0 + nq];
        }
        __syncthreads();
#pragma unroll
        for (int k = 0; k < 16; ++k) {
            float4 a = *(const float4*)&As[k][ty*4];
            float4 bv = *(const float4*)&Bs[k][tx*4];
            float av[4] = {a.x, a.y, a.z, a.w};
            float bb[4] = {bv.x, bv.y, bv.z, bv.w};
#pragma unroll
            for (int u = 0; u < 4; ++u)
#pragma unroll
                for (int v2 = 0; v2 < 4; ++v2)
                    acc[u][v2] = fmaf(av[u], bb[v2], acc[u][v2]);
        }
        __syncthreads();
    }
#pragma unroll
    for (int u = 0; u < 4; ++u) {
        int row = m0 + ty*4 + u;
        float d = dinv(Sp[row]);
        float4 o = make_float4(tf32_rn(acc[u][0]*d), tf32_rn(acc[u][1]*d),
                               tf32_rn(acc[u][2]*d), tf32_rn(acc[u][3]*d));
        *(float4*)&P[(size_t)row*F0 + tx*4] = o;
    }
}

// ---------------- Y_s = D_s*(A_s @ P_s + P_s) — TF32 MMA, in-block split-K ----------------
__global__ __launch_bounds__(256) void k_LL_mma(const float* __restrict__ Ain) {
    int m0 = blockIdx.x*64;
    int z = blockIdx.y, b = z >> 1, s = z & 1;
    const float* Am = (s ? g_Ap : Ain) + (size_t)b*NN*NN;
    const float* P  = (s ? g_P1 : g_P0) + (size_t)b*NN*F0;
    float* Y        = (s ? g_Y1 : g_Y0) + (size_t)b*NN*F0;
    const float* Sp = (s ? g_S1 : g_S0) + b*NN;

    __shared__ float As[2][16][72];
    __shared__ float Bs[2][16][72];
    __shared__ float red[4096];
    int t = threadIdx.x;
    int lane = t & 31, warp = t >> 5;
    int gq = warp >> 2, wg = warp & 3;
    int g = lane >> 2, tig = lane & 3;
    int wm = wg >> 1, wn = wg & 1;
    int tg = t & 127;

    float acc[2][4][4] = {};

    int qa0 = tg*2, qa1 = tg*2 + 1;
    int ar0 = qa0 >> 2, akq0 = (qa0 & 3)*4;
    int ar1 = qa1 >> 2, akq1 = (qa1 & 3)*4;
    int bk0 = qa0 >> 4, bnq0 = (qa0 & 15)*4;
    int bk1 = qa1 >> 4, bnq1 = (qa1 & 15)*4;

    int kstart = gq*16;
    float4 aR0 = *(const float4*)&Am[(size_t)(m0+ar0)*NN + kstart + akq0];
    float4 aR1 = *(const float4*)&Am[(size_t)(m0+ar1)*NN + kstart + akq1];
    float4 bR0 = *(const float4*)&P[(size_t)(kstart+bk0)*F0 + bnq0];
    float4 bR1 = *(const float4*)&P[(size_t)(kstart+bk1)*F0 + bnq1];

    for (int k0 = kstart; k0 < NN; k0 += 32) {
        As[gq][akq0+0][ar0] = tf32_rn(aR0.x); As[gq][akq0+1][ar0] = tf32_rn(aR0.y);
        As[gq][akq0+2][ar0] = tf32_rn(aR0.z); As[gq][akq0+3][ar0] = tf32_rn(aR0.w);
        As[gq][akq1+0][ar1] = tf32_rn(aR1.x); As[gq][akq1+1][ar1] = tf32_rn(aR1.y);
        As[gq][akq1+2][ar1] = tf32_rn(aR1.z); As[gq][akq1+3][ar1] = tf32_rn(aR1.w);
        Bs[gq][bk0][bnq0+0] = bR0.x; Bs[gq][bk0][bnq0+1] = bR0.y;
        Bs[gq][bk0][bnq0+2] = bR0.z; Bs[gq][bk0][bnq0+3] = bR0.w;
        Bs[gq][bk1][bnq1+0] = bR1.x; Bs[gq][bk1][bnq1+1] = bR1.y;
        Bs[gq][bk1][bnq1+2] = bR1.z; Bs[gq][bk1][bnq1+3] = bR1.w;
        __syncthreads();

        if (k0 + 32 < NN) {
            int kn = k0 + 32;
            aR0 = *(const float4*)&Am[(size_t)(m0+ar0)*NN + kn + akq0];
            aR1 = *(const float4*)&Am[(size_t)(m0+ar1)*NN + kn + akq1];
            bR0 = *(const float4*)&P[(size_t)(kn+bk0)*F0 + bnq0];
            bR1 = *(const float4*)&P[(size_t)(kn+bk1)*F0 + bnq1];
        }

#pragma unroll
        for (int kb = 0; kb < 16; kb += 8) {
            uint32_t af[2][4], bf[4][2];
#pragma unroll
            for (int mt = 0; mt < 2; ++mt) {
                int m = wm*32 + mt*16 + g;
                af[mt][0] = __float_as_uint(As[gq][kb+tig  ][m]);
                af[mt][1] = __float_as_uint(As[gq][kb+tig  ][m+8]);
                af[mt][2] = __float_as_uint(As[gq][kb+tig+4][m]);
                af[mt][3] = __float_as_uint(As[gq][kb+tig+4][m+8]);
            }
#pragma unroll
            for (int nt = 0; nt < 4; ++nt) {
                int n = wn*32 + nt*8 + g;
                bf[nt][0] = __float_as_uint(Bs[gq][kb+tig  ][n]);
                bf[nt][1] = __float_as_uint(Bs[gq][kb+tig+4][n]);
            }
#pragma unroll
            for (int mt = 0; mt < 2; ++mt)
#pragma unroll
                for (int nt = 0; nt < 4; ++nt)
                    mma_tf32(acc[mt][nt], af[mt], bf[nt]);
        }
        __syncthreads();
    }

    if (gq == 1) {
#pragma unroll
        for (int mt = 0; mt < 2; ++mt)
#pragma unroll
            for (int nt = 0; nt < 4; ++nt)
                *(float4*)&red[(((wg*2+mt)*4+nt)*32 + lane)*4] =
                    make_float4(acc[mt][nt][0], acc[mt][nt][1], acc[mt][nt][2], acc[mt][nt][3]);
    }
    __syncthreads();
    if (gq == 0) {
#pragma unroll
        for (int mt = 0; mt < 2; ++mt)
#pragma unroll
            for (int nt = 0; nt < 4; ++nt) {
                float4 rv = *(const float4*)&red[(((wg*2+mt)*4+nt)*32 + lane)*4];
                float c0 = acc[mt][nt][0] + rv.x;
                float c1 = acc[mt][nt][1] + rv.y;
                float c2 = acc[mt][nt][2] + rv.z;
                float c3 = acc[mt][nt][3] + rv.w;
                int r0 = m0 + wm*32 + mt*16 + g;
                int cc = wn*32 + nt*8 + 2*tig;
                float d0 = dinv(Sp[r0]), d8 = dinv(Sp[r0+8]);
                float2 p0 = *(const float2*)&P[(size_t)r0*F0 + cc];
                float2 p8 = *(const float2*)&P[(size_t)(r0+8)*F0 + cc];
                *(float2*)&Y[(size_t)r0*F0 + cc]     = make_float2(d0*(c0 + p0.x), d0*(c1 + p0.y));
                *(float2*)&Y[(size_t)(r0+8)*F0 + cc] = make_float2(d8*(c2 + p8.x), d8*(c3 + p8.y));
            }
    }
}

// ---------------- final: h = relu((Y0+Y1+gb2)*mask); g = max; out = g@fcw + fcb ----------------
__global__ __launch_bounds__(512) void k_final(const float* __restrict__ gb2,
                                               const float* __restrict__ mask,
                                               const float* __restrict__ fcw,
                                               const float* __restrict__ fcb,
                                               float* __restrict__ out) {
    int b = blockIdx.x;
    int f = threadIdx.x & 63;
    int ty = threadIdx.x >> 6;
    float bf = gb2[f];
    float m = -FLT_MAX;
    for (int i = ty; i < NN; i += 8) {
        int row = b*NN + i;
        float h = fmaxf((g_Y0[(size_t)row*F0 + f] + g_Y1[(size_t)row*F0 + f] + bf)*mask[row], 0.f);
        m = fmaxf(m, h);
    }
    __shared__ float red[8][64];
    __shared__ float gs[F0];
    red[ty][f] = m;
    __syncthreads();
    if (ty == 0) {
        float mm = red[0][f];
#pragma unroll
        for (int q = 1; q < 8; ++q) mm = fmaxf(mm, red[q][f]);
        gs[f] = mm;
    }
    __syncthreads();
    if (threadIdx.x < OUTD) {
        float acc = fcb[threadIdx.x];
#pragma unroll
        for (int q = 0; q < F0; ++q) acc = fmaf(gs[q], fcw[q*OUTD + threadIdx.x], acc);
        out[b*OUTD + threadIdx.x] = acc;
    }
}

// ---------------- launch ----------------
extern "C" void kernel_launch(void* const* d_in, const int* in_sizes, int n_in,
                              void* d_out, int out_size) {
    const float* x    = (const float*)d_in[0];
    const float* A    = (const float*)d_in[1];
    const float* mask = (const float*)d_in[2];
    const float* ew1  = (const float*)d_in[3];
    const float* eb1  = (const float*)d_in[4];
    const float* ew2  = (const float*)d_in[5];
    const float* eb2  = (const float*)d_in[6];
    const float* gw0  = (const float*)d_in[7];
    const float* gb0  = (const float*)d_in[8];
    const float* gw1  = (const float*)d_in[9];
    const float* gb1  = (const float*)d_in[10];
    const float* gw2  = (const float*)d_in[11];
    const float* gb2  = (const float*)d_in[12];
    const float* fcw  = (const float*)d_in[13];
    const float* fcb  = (const float*)d_in[14];
    float* out = (float*)d_out;

    k_zeroS<<<16, 256>>>();                                  // 1
    k_xab<<<MTOT/64, 256>>>(x, ew1, eb1);                    // 2
    k_colsumA<<<dim3(64, BB), 256>>>(A);                     // 3
    k_edge_sym<<<dim3(136, BB), dim3(32, 8)>>>(mask, ew2, eb2); // 4 (profiled slot)

    // layer 0
    k_proj<<<dim3(MTOT/64, 2), 256>>>(x, nullptr, gw0, mask, 0, CC);
    k_LL_mma<<<dim3(NN/64, BB*2), 256>>>(A);
    // layer 1
    k_proj<<<dim3(MTOT/64, 2), 256>>>(nullptr, gb0, gw1, mask, 1, F0);
    k_LL_mma<<<dim3(NN/64, BB*2), 256>>>(A);
    // layer 2
    k_proj<<<dim3(MTOT/64, 2), 256>>>(nullptr, gb1, gw2, mask, 1, F0);
    k_LL_mma<<<dim3(NN/64, BB*2), 256>>>(A);

    k_final<<<BB, 512>>>(gb2, mask, fcw, fcb, out);

    (void)in_sizes; (void)n_in; (void)out_size;
}

// round 7
// speedup vs baseline: 1.0949x; 1.0949x over previous
#include <cuda_runtime.h>
#include <math.h>
#include <float.h>
#include <stdint.h>

#define BB   8
#define NN   512
#define CC   256
#define HE   32
#define F0   64
#define OUTD 2
#define MTOT (BB*NN)   // 4096

// ---------------- scratch (device globals; no allocations) ----------------
__device__ float g_xab[MTOT*64];     // [xa | xb+eb1] per row
__device__ float g_Ap[BB*NN*NN];     // raw A_pred (8 MB)
__device__ float g_S0[MTOT];
__device__ float g_S1[MTOT];
__device__ float g_P0[MTOT*F0];      // D-scaled projections (tf32-rounded)
__device__ float g_P1[MTOT*F0];
__device__ float g_Y0[MTOT*F0];
__device__ float g_Y1[MTOT*F0];

// ---------------- helpers ----------------
__device__ __forceinline__ float tf32_rn(float x) {
    uint32_t u;
    asm("cvt.rna.tf32.f32 %0, %1;" : "=r"(u) : "f"(x));
    return __uint_as_float(u);
}
__device__ __forceinline__ void mma_tf32(float c[4], const uint32_t a[4], const uint32_t b[2]) {
    asm volatile(
        "mma.sync.aligned.m16n8k8.row.col.f32.tf32.tf32.f32 "
        "{%0,%1,%2,%3}, {%4,%5,%6,%7}, {%8,%9}, {%0,%1,%2,%3};\n"
        : "+f"(c[0]), "+f"(c[1]), "+f"(c[2]), "+f"(c[3])
        : "r"(a[0]), "r"(a[1]), "r"(a[2]), "r"(a[3]), "r"(b[0]), "r"(b[1]));
}
__device__ __forceinline__ float dinv(float s) { return rsqrtf(s + 1.0f + 1e-5f); }
__device__ __forceinline__ void barg(int id) {
    asm volatile("bar.sync %0, 128;" :: "r"(id) : "memory");
}

// ---------------- zero colsum accumulators ----------------
__global__ __launch_bounds__(256) void k_zeroS() {
    int i = blockIdx.x*256 + threadIdx.x;
    if (i < MTOT) { g_S0[i] = 0.f; g_S1[i] = 0.f; }
}

// ---------------- g_xab = x @ [wa | wb], eb1 folded into cols 32..63 ----------------
__global__ __launch_bounds__(256) void k_xab(const float* __restrict__ x,
                                             const float* __restrict__ ew1,
                                             const float* __restrict__ eb1) {
    int m0 = blockIdx.x*64;
    __shared__ float As[16][64];
    __shared__ float Bs[16][64];
    int t = threadIdx.x;
    int tx = t & 15, ty = t >> 4;
    float acc[4][4] = {};

    for (int k0 = 0; k0 < CC; k0 += 16) {
        {
            int row = t >> 2, kq = (t & 3)*4;
            float4 v = *(const float4*)&x[(size_t)(m0+row)*CC + k0 + kq];
            As[kq+0][row] = v.x; As[kq+1][row] = v.y; As[kq+2][row] = v.z; As[kq+3][row] = v.w;
        }
        {
            int kk = t >> 4, nq = (t & 15)*4;
            const float* src = (nq < 32) ? &ew1[(size_t)(k0+kk)*HE + nq]
                                         : &ew1[(size_t)(k0+kk+CC)*HE + nq - 32];
            *(float4*)&Bs[kk][nq] = *(const float4*)src;
        }
        __syncthreads();
#pragma unroll
        for (int k = 0; k < 16; ++k) {
            float4 a = *(const float4*)&As[k][ty*4];
            float4 bv = *(const float4*)&Bs[k][tx*4];
            float av[4] = {a.x, a.y, a.z, a.w};
            float bb[4] = {bv.x, bv.y, bv.z, bv.w};
#pragma unroll
            for (int u = 0; u < 4; ++u)
#pragma unroll
                for (int v2 = 0; v2 < 4; ++v2)
                    acc[u][v2] = fmaf(av[u], bb[v2], acc[u][v2]);
        }
        __syncthreads();
    }
#pragma unroll
    for (int u = 0; u < 4; ++u) {
        int row = m0 + ty*4 + u;
        float o[4];
#pragma unroll
        for (int v2 = 0; v2 < 4; ++v2) {
            int col = tx*4 + v2;
            o[v2] = acc[u][v2] + (col >= 32 ? eb1[col-32] : 0.f);
        }
        *(float4*)&g_xab[(size_t)row*64 + tx*4] = make_float4(o[0], o[1], o[2], o[3]);
    }
}

// ---------------- colsum of input A ----------------
__global__ __launch_bounds__(256) void k_colsumA(const float* __restrict__ A) {
    int b = blockIdx.y, r0 = blockIdx.x*8;
    int t = threadIdx.x;
    float a0 = 0.f, a1 = 0.f;
    const float* base = A + ((size_t)b*NN + r0)*NN;
#pragma unroll
    for (int r = 0; r < 8; ++r) {
        a0 += base[r*NN + t];
        a1 += base[r*NN + t + 256];
    }
    atomicAdd(&g_S0[b*NN + t],       a0);
    atomicAdd(&g_S0[b*NN + t + 256], a1);
}

// ---------------- fused edge-MLP + symmetrize + exp + mask + colsum(S1) ----------------
// Feature-major smem tiles (stride 33): j-side reads stride-1, i-side broadcast.
// Low register pressure for high occupancy.
__global__ __launch_bounds__(256) void k_edge_sym(const float* __restrict__ mask,
                                                  const float* __restrict__ ew2,
                                                  const float* __restrict__ eb2) {
    int idx = blockIdx.x, bi = 0;
    while (idx >= 16 - bi) { idx -= 16 - bi; ++bi; }
    int bj = bi + idx;
    int b = blockIdx.y;
    int i0 = bi*32, j0 = bj*32;
    bool diag = (bi == bj);
    __shared__ float si[64][33], sj[64][33];   // [feature][node]
    __shared__ float w[32], mi_s[32], mj_s[32];
    __shared__ float red[8][32];
    int tx = threadIdx.x, ty = threadIdx.y;
    int t = ty*32 + tx;
    for (int q = t; q < 512; q += 256) {
        int node = q >> 4, c = (q & 15)*4;
        float4 vi = *(const float4*)&g_xab[(size_t)(b*NN + i0 + node)*64 + c];
        si[c+0][node] = vi.x; si[c+1][node] = vi.y; si[c+2][node] = vi.z; si[c+3][node] = vi.w;
        float4 vj = *(const float4*)&g_xab[(size_t)(b*NN + j0 + node)*64 + c];
        sj[c+0][node] = vj.x; sj[c+1][node] = vj.y; sj[c+2][node] = vj.z; sj[c+3][node] = vj.w;
    }
    if (t < 32) { w[t] = ew2[t]; mi_s[t] = mask[b*NN + i0 + t]; mj_s[t] = mask[b*NN + j0 + t]; }
    __syncthreads();

    float e2v = eb2[0];
    float acc1[4], acc2[4];
#pragma unroll
    for (int r = 0; r < 4; ++r) { acc1[r] = e2v; acc2[r] = e2v; }

#pragma unroll 8
    for (int k = 0; k < 32; ++k) {
        float wk  = w[k];
        float ajv = sj[k][tx];        // xa_j   (stride-1, conflict-free)
        float bjv = sj[32+k][tx];     // xb_j+eb1
#pragma unroll
        for (int r = 0; r < 4; ++r) {
            int il = ty + r*8;
            float aiv = si[k][il];        // broadcast
            float biv = si[32+k][il];     // broadcast
            acc1[r] = fmaf(fmaxf(aiv + bjv, 0.f), wk, acc1[r]);
            acc2[r] = fmaf(fmaxf(ajv + biv, 0.f), wk, acc2[r]);
        }
    }

    float colacc = 0.f;
#pragma unroll
    for (int r = 0; r < 4; ++r) {
        int il = ty + r*8, jl = tx;
        int gi = i0 + il, gj = j0 + jl;
        float v = 0.f;
        if (gi != gj && mi_s[il] > 0.f && mj_s[jl] > 0.f)
            v = __expf(0.5f*(acc1[r] + acc2[r]));
        g_Ap[((size_t)b*NN + gi)*NN + gj] = v;
        colacc += v;
        if (!diag) {
            g_Ap[((size_t)b*NN + gj)*NN + gi] = v;
            float rs = v;
#pragma unroll
            for (int off = 16; off; off >>= 1) rs += __shfl_xor_sync(0xffffffffu, rs, off);
            if (tx == 0) atomicAdd(&g_S1[b*NN + gi], rs);
        }
    }
    red[ty][tx] = colacc;
    __syncthreads();
    if (ty == 0) {
        float tot = 0.f;
#pragma unroll
        for (int q = 0; q < 8; ++q) tot += red[q][tx];
        atomicAdd(&g_S1[b*NN + j0 + tx], tot);
    }
}

// ---------------- projection: P_s = tf32(D_s * (h @ W_s)), D inline ----------------
__global__ __launch_bounds__(256) void k_proj(const float* __restrict__ xin,
                                              const float* __restrict__ biasPrev,
                                              const float* __restrict__ W,
                                              const float* __restrict__ mask,
                                              int mode, int K) {
    int m0 = blockIdx.x*64;
    int s = blockIdx.y;
    const float* Wp = W + (size_t)s*K*F0;
    const float* Sp = s ? g_S1 : g_S0;
    float* P = s ? g_P1 : g_P0;

    __shared__ float As[16][64];
    __shared__ float Bs[16][64];
    int t = threadIdx.x;
    int tx = t & 15, ty = t >> 4;
    float acc[4][4] = {};

    for (int k0 = 0; k0 < K; k0 += 16) {
        {
            int row = t >> 2, kq = (t & 3)*4;
            int grow = m0 + row;
            float4 v;
            if (mode == 0) {
                v = *(const float4*)&xin[(size_t)grow*CC + k0 + kq];
            } else {
                float4 y0 = *(const float4*)&g_Y0[(size_t)grow*F0 + k0 + kq];
                float4 y1 = *(const float4*)&g_Y1[(size_t)grow*F0 + k0 + kq];
                float4 bp = *(const float4*)&biasPrev[k0 + kq];
                float mk = mask[grow];
                v.x = fmaxf((y0.x + y1.x + bp.x)*mk, 0.f);
                v.y = fmaxf((y0.y + y1.y + bp.y)*mk, 0.f);
                v.z = fmaxf((y0.z + y1.z + bp.z)*mk, 0.f);
                v.w = fmaxf((y0.w + y1.w + bp.w)*mk, 0.f);
            }
            As[kq+0][row] = v.x; As[kq+1][row] = v.y; As[kq+2][row] = v.z; As[kq+3][row] = v.w;
        }
        {
            int kk = t >> 4, nq = (t & 15)*4;
            *(float4*)&Bs[kk][nq] = *(const float4*)&Wp[(size_t)(k0+kk)*F0 + nq];
        }
        __syncthreads();
#pragma unroll
        for (int k = 0; k < 16; ++k) {
            float4 a = *(const float4*)&As[k][ty*4];
            float4 bv = *(const float4*)&Bs[k][tx*4];
            float av[4] = {a.x, a.y, a.z, a.w};
            float bb[4] = {bv.x, bv.y, bv.z, bv.w};
#pragma unroll
            for (int u = 0; u < 4; ++u)
#pragma unroll
                for (int v2 = 0; v2 < 4; ++v2)
                    acc[u][v2] = fmaf(av[u], bb[v2], acc[u][v2]);
        }
        __syncthreads();
    }
#pragma unroll
    for (int u = 0; u < 4; ++u) {
        int row = m0 + ty*4 + u;
        float d = dinv(Sp[row]);
        float4 o = make_float4(tf32_rn(acc[u][0]*d), tf32_rn(acc[u][1]*d),
                               tf32_rn(acc[u][2]*d), tf32_rn(acc[u][3]*d));
        *(float4*)&P[(size_t)row*F0 + tx*4] = o;
    }
}

// ---------------- Y_s = D_s*(A_s @ P_s + P_s) — TF32 MMA, in-block split-K ----------------
// Two 4-warp groups with private smem tiles and group-scoped named barriers.
__global__ __launch_bounds__(256) void k_LL_mma(const float* __restrict__ Ain) {
    int m0 = blockIdx.x*64;
    int z = blockIdx.y, b = z >> 1, s = z & 1;
    const float* Am = (s ? g_Ap : Ain) + (size_t)b*NN*NN;
    const float* P  = (s ? g_P1 : g_P0) + (size_t)b*NN*F0;
    float* Y        = (s ? g_Y1 : g_Y0) + (size_t)b*NN*F0;
    const float* Sp = (s ? g_S1 : g_S0) + b*NN;

    __shared__ float As[2][16][72];
    __shared__ float Bs[2][16][72];
    __shared__ float red[4096];
    int t = threadIdx.x;
    int lane = t & 31, warp = t >> 5;
    int gq = warp >> 2, wg = warp & 3;
    int g = lane >> 2, tig = lane & 3;
    int wm = wg >> 1, wn = wg & 1;
    int tg = t & 127;
    int barid = gq + 1;

    float acc[2][4][4] = {};

    int qa0 = tg*2, qa1 = tg*2 + 1;
    int ar0 = qa0 >> 2, akq0 = (qa0 & 3)*4;
    int ar1 = qa1 >> 2, akq1 = (qa1 & 3)*4;
    int bk0 = qa0 >> 4, bnq0 = (qa0 & 15)*4;
    int bk1 = qa1 >> 4, bnq1 = (qa1 & 15)*4;

    int kstart = gq*16;
    float4 aR0 = *(const float4*)&Am[(size_t)(m0+ar0)*NN + kstart + akq0];
    float4 aR1 = *(const float4*)&Am[(size_t)(m0+ar1)*NN + kstart + akq1];
    float4 bR0 = *(const float4*)&P[(size_t)(kstart+bk0)*F0 + bnq0];
    float4 bR1 = *(const float4*)&P[(size_t)(kstart+bk1)*F0 + bnq1];

    for (int k0 = kstart; k0 < NN; k0 += 32) {
        As[gq][akq0+0][ar0] = tf32_rn(aR0.x); As[gq][akq0+1][ar0] = tf32_rn(aR0.y);
        As[gq][akq0+2][ar0] = tf32_rn(aR0.z); As[gq][akq0+3][ar0] = tf32_rn(aR0.w);
        As[gq][akq1+0][ar1] = tf32_rn(aR1.x); As[gq][akq1+1][ar1] = tf32_rn(aR1.y);
        As[gq][akq1+2][ar1] = tf32_rn(aR1.z); As[gq][akq1+3][ar1] = tf32_rn(aR1.w);
        Bs[gq][bk0][bnq0+0] = bR0.x; Bs[gq][bk0][bnq0+1] = bR0.y;
        Bs[gq][bk0][bnq0+2] = bR0.z; Bs[gq][bk0][bnq0+3] = bR0.w;
        Bs[gq][bk1][bnq1+0] = bR1.x; Bs[gq][bk1][bnq1+1] = bR1.y;
        Bs[gq][bk1][bnq1+2] = bR1.z; Bs[gq][bk1][bnq1+3] = bR1.w;
        barg(barid);

        if (k0 + 32 < NN) {
            int kn = k0 + 32;
            aR0 = *(const float4*)&Am[(size_t)(m0+ar0)*NN + kn + akq0];
            aR1 = *(const float4*)&Am[(size_t)(m0+ar1)*NN + kn + akq1];
            bR0 = *(const float4*)&P[(size_t)(kn+bk0)*F0 + bnq0];
            bR1 = *(const float4*)&P[(size_t)(kn+bk1)*F0 + bnq1];
        }

#pragma unroll
        for (int kb = 0; kb < 16; kb += 8) {
            uint32_t af[2][4], bf[4][2];
#pragma unroll
            for (int mt = 0; mt < 2; ++mt) {
                int m = wm*32 + mt*16 + g;
                af[mt][0] = __float_as_uint(As[gq][kb+tig  ][m]);
                af[mt][1] = __float_as_uint(As[gq][kb+tig  ][m+8]);
                af[mt][2] = __float_as_uint(As[gq][kb+tig+4][m]);
                af[mt][3] = __float_as_uint(As[gq][kb+tig+4][m+8]);
            }
#pragma unroll
            for (int nt = 0; nt < 4; ++nt) {
                int n = wn*32 + nt*8 + g;
                bf[nt][0] = __float_as_uint(Bs[gq][kb+tig  ][n]);
                bf[nt][1] = __float_as_uint(Bs[gq][kb+tig+4][n]);
            }
#pragma unroll
            for (int mt = 0; mt < 2; ++mt)
#pragma unroll
                for (int nt = 0; nt < 4; ++nt)
                    mma_tf32(acc[mt][nt], af[mt], bf[nt]);
        }
        barg(barid);
    }

    if (gq == 1) {
#pragma unroll
        for (int mt = 0; mt < 2; ++mt)
#pragma unroll
            for (int nt = 0; nt < 4; ++nt)
                *(float4*)&red[(((wg*2+mt)*4+nt)*32 + lane)*4] =
                    make_float4(acc[mt][nt][0], acc[mt][nt][1], acc[mt][nt][2], acc[mt][nt][3]);
    }
    __syncthreads();
    if (gq == 0) {
#pragma unroll
        for (int mt = 0; mt < 2; ++mt)
#pragma unroll
            for (int nt = 0; nt < 4; ++nt) {
                float4 rv = *(const float4*)&red[(((wg*2+mt)*4+nt)*32 + lane)*4];
                float c0 = acc[mt][nt][0] + rv.x;
                float c1 = acc[mt][nt][1] + rv.y;
                float c2 = acc[mt][nt][2] + rv.z;
                float c3 = acc[mt][nt][3] + rv.w;
                int r0 = m0 + wm*32 + mt*16 + g;
                int cc = wn*32 + nt*8 + 2*tig;
                float d0 = dinv(Sp[r0]), d8 = dinv(Sp[r0+8]);
                float2 p0 = *(const float2*)&P[(size_t)r0*F0 + cc];
                float2 p8 = *(const float2*)&P[(size_t)(r0+8)*F0 + cc];
                *(float2*)&Y[(size_t)r0*F0 + cc]     = make_float2(d0*(c0 + p0.x), d0*(c1 + p0.y));
                *(float2*)&Y[(size_t)(r0+8)*F0 + cc] = make_float2(d8*(c2 + p8.x), d8*(c3 + p8.y));
            }
    }
}

// ---------------- final: h = relu((Y0+Y1+gb2)*mask); g = max; out = g@fcw + fcb ----------------
__global__ __launch_bounds__(512) void k_final(const float* __restrict__ gb2,
                                               const float* __restrict__ mask,
                                               const float* __restrict__ fcw,
                                               const float* __restrict__ fcb,
                                               float* __restrict__ out) {
    int b = blockIdx.x;
    int f = threadIdx.x & 63;
    int ty = threadIdx.x >> 6;
    float bf = gb2[f];
    float m = -FLT_MAX;
    for (int i = ty; i < NN; i += 8) {
        int row = b*NN + i;
        float h = fmaxf((g_Y0[(size_t)row*F0 + f] + g_Y1[(size_t)row*F0 + f] + bf)*mask[row], 0.f);
        m = fmaxf(m, h);
    }
    __shared__ float red[8][64];
    __shared__ float gs[F0];
    red[ty][f] = m;
    __syncthreads();
    if (ty == 0) {
        float mm = red[0][f];
#pragma unroll
        for (int q = 1; q < 8; ++q) mm = fmaxf(mm, red[q][f]);
        gs[f] = mm;
    }
    __syncthreads();
    if (threadIdx.x < OUTD) {
        float acc = fcb[threadIdx.x];
#pragma unroll
        for (int q = 0; q < F0; ++q) acc = fmaf(gs[q], fcw[q*OUTD + threadIdx.x], acc);
        out[b*OUTD + threadIdx.x] = acc;
    }
}

// ---------------- launch ----------------
extern "C" void kernel_launch(void* const* d_in, const int* in_sizes, int n_in,
                              void* d_out, int out_size) {
    const float* x    = (const float*)d_in[0];
    const float* A    = (const float*)d_in[1];
    const float* mask = (const float*)d_in[2];
    const float* ew1  = (const float*)d_in[3];
    const float* eb1  = (const float*)d_in[4];
    const float* ew2  = (const float*)d_in[5];
    const float* eb2  = (const float*)d_in[6];
    const float* gw0  = (const float*)d_in[7];
    const float* gb0  = (const float*)d_in[8];
    const float* gw1  = (const float*)d_in[9];
    const float* gb1  = (const float*)d_in[10];
    const float* gw2  = (const float*)d_in[11];
    const float* gb2  = (const float*)d_in[12];
    const float* fcw  = (const float*)d_in[13];
    const float* fcb  = (const float*)d_in[14];
    float* out = (float*)d_out;

    k_zeroS<<<16, 256>>>();                                     // 1
    k_xab<<<MTOT/64, 256>>>(x, ew1, eb1);                       // 2
    k_colsumA<<<dim3(64, BB), 256>>>(A);                        // 3
    k_edge_sym<<<dim3(136, BB), dim3(32, 8)>>>(mask, ew2, eb2); // 4 (profiled slot)

    // layer 0
    k_proj<<<dim3(MTOT/64, 2), 256>>>(x, nullptr, gw0, mask, 0, CC);
    k_LL_mma<<<dim3(NN/64, BB*2), 256>>>(A);
    // layer 1
    k_proj<<<dim3(MTOT/64, 2), 256>>>(nullptr, gb0, gw1, mask, 1, F0);
    k_LL_mma<<<dim3(NN/64, BB*2), 256>>>(A);
    // layer 2
    k_proj<<<dim3(MTOT/64, 2), 256>>>(nullptr, gb1, gw2, mask, 1, F0);
    k_LL_mma<<<dim3(NN/64, BB*2), 256>>>(A);

    k_final<<<BB, 512>>>(gb2, mask, fcw, fcb, out);

    (void)in_sizes; (void)n_in; (void)out_size;
}